// round 16
// baseline (speedup 1.0000x reference)
#include <cuda_runtime.h>
#include <cuda_fp16.h>
#include <math.h>

#define BB 8
#define TT 4096
#define CC 512
#define HH 512
#define NOUT 1536
#define NC 128
#define LCH 32

#define BM 128
#define BN 128
#define BK 32                 // halves per k-tile
#define NKT 16                // 512 / 32
#define STG 3
#define XPAD 20               // row stride in b32 units (conflict-free, 16B-aligned)
#define SX_U32 (129 * XPAD)   // 2580
#define SW_U32 (256 * XPAD)   // 5120
#define STAGE_U32 (SX_U32 + SW_U32)
#define SMEM_BYTES (STG * STAGE_U32 * 4)

#define XBLKS (BB * TT * CC / 8 / 256)     // 8192
#define WBLKS (2 * NOUT * CC / 256)        // 6144

// -------- scratch --------
__device__ __align__(16) __half g_xh [(size_t)BB * TT * CC];      // fp16 input x
__device__ __align__(16) __half g_xh2[(size_t)BB * TT * CC];      // fp16 layer-1 output
__device__ __align__(16) __half g_wh [(size_t)2 * 2 * NOUT * CC]; // [layer][tap][n][c]
__device__ __align__(16) __half g_z  [(size_t)BB * TT * HH];      // tanh(z)   fp16
__device__ __align__(16) __half g_fh [(size_t)BB * TT * HH];      // sig(f)    fp16
__device__ __align__(16) __half g_o  [(size_t)BB * TT * HH];      // sig(o)    fp16
__device__ __align__(16) float  g_cA [BB * NC * HH];
__device__ __align__(16) float  g_cB [BB * NC * HH];
__device__ __align__(16) float  g_hs [BB * NC * HH];
__device__ unsigned g_cnt[BB];   // zero-init; combiner resets -> graph-replay safe

__device__ __forceinline__ void cpa16(unsigned* dst_smem_word, const void* src, bool pred) {
    unsigned d = (unsigned)__cvta_generic_to_shared(dst_smem_word);
    int sz = pred ? 16 : 0;
    asm volatile("cp.async.cg.shared.global [%0], [%1], 16, %2;\n"
                 :: "r"(d), "l"(src), "r"(sz) : "memory");
}

__device__ __forceinline__ void mma16(float* c, const unsigned* a, unsigned b0, unsigned b1) {
    asm volatile(
        "mma.sync.aligned.m16n8k16.row.col.f32.f16.f16.f32 "
        "{%0,%1,%2,%3}, {%4,%5,%6,%7}, {%8,%9}, {%0,%1,%2,%3};\n"
        : "+f"(c[0]), "+f"(c[1]), "+f"(c[2]), "+f"(c[3])
        : "r"(a[0]), "r"(a[1]), "r"(a[2]), "r"(a[3]), "r"(b0), "r"(b1));
}

__device__ __forceinline__ void ldsm4(unsigned* r, unsigned addr) {
    asm volatile("ldmatrix.sync.aligned.m8n8.x4.shared.b16 {%0,%1,%2,%3}, [%4];"
                 : "=r"(r[0]), "=r"(r[1]), "=r"(r[2]), "=r"(r[3]) : "r"(addr));
}

// fast activations: EX2-based exp + MUFU.RCP division
__device__ __forceinline__ float fsigmoid(float x) {
    return __fdividef(1.0f, 1.0f + __expf(-x));
}
__device__ __forceinline__ float ftanh(float x) {
    return 2.0f * __fdividef(1.0f, 1.0f + __expf(-2.0f * x)) - 1.0f;
}

// ---------------- prep: fp16 conversion (x and w fused) ----------------
__global__ void cvt_in(const float* __restrict__ x,
                       const float* __restrict__ w0, const float* __restrict__ w1) {
    int bid = blockIdx.x;
    if (bid < XBLKS) {
        int gid = bid * blockDim.x + threadIdx.x;
        float4 v0 = ((const float4*)x)[gid * 2];
        float4 v1 = ((const float4*)x)[gid * 2 + 1];
        __half2 h0 = __floats2half2_rn(v0.x, v0.y);
        __half2 h1 = __floats2half2_rn(v0.z, v0.w);
        __half2 h2 = __floats2half2_rn(v1.x, v1.y);
        __half2 h3 = __floats2half2_rn(v1.z, v1.w);
        uint4 o;
        o.x = *(unsigned*)&h0; o.y = *(unsigned*)&h1;
        o.z = *(unsigned*)&h2; o.w = *(unsigned*)&h3;
        ((uint4*)g_xh)[gid] = o;
    } else {
        int gid = (bid - XBLKS) * blockDim.x + threadIdx.x;   // 0 .. 2*NOUT*CC-1
        int layer = gid >= NOUT * CC;
        int r = gid - layer * NOUT * CC;
        int n = r / CC, c = r % CC;
        const float* w = layer ? w1 : w0;
        float2 v = *(const float2*)(w + ((size_t)n * CC + c) * 2);
        g_wh[(((size_t)layer * 2 + 0) * NOUT + n) * CC + c] = __float2half_rn(v.x); // tap0
        g_wh[(((size_t)layer * 2 + 1) * NOUT + n) * CC + c] = __float2half_rn(v.y); // tap1
    }
}

// ---------------- fp16 HMMA GEMM + activation ----------------
// grid (12, 256): x = N-tile (fast: shares A stripe via L2), y = M-tile. block 256.
// 8 warps in 2(M) x 4(N), warp tile 64x32, acc 64 regs -> 2 CTAs/SM.
__global__ void __launch_bounds__(256, 2) qrnn_gemm(int layer, const float* __restrict__ bias)
{
    extern __shared__ unsigned smem[];

    const __half* X  = layer ? g_xh2 : g_xh;
    const __half* Wl = g_wh + (size_t)layer * 2 * NOUT * CC;

    const int tid  = threadIdx.x;
    const int nt   = blockIdx.x;
    const int mt   = blockIdx.y;
    const int b    = mt >> 5;
    const int t0   = (mt & 31) * BM;
    const int warp = tid >> 5, lane = tid & 31;
    const int wm   = warp >> 2, wn = warp & 3;
    const int gr   = lane >> 2, tg = lane & 3;

    const __half* Xb = X + (size_t)b * TT * CC;

    float acc[4][4][4];
#pragma unroll
    for (int i = 0; i < 4; i++)
#pragma unroll
        for (int j = 0; j < 4; j++)
#pragma unroll
            for (int q = 0; q < 4; q++) acc[i][j][q] = 0.0f;

    // ---- per-lane ldmatrix base addresses (bytes into stage 0) ----
    const unsigned smem_b = (unsigned)__cvta_generic_to_shared(smem);
    const int a_off = (wm * 64 + (lane & 7) + ((lane >> 3) & 1) * 8) * XPAD
                    + ((lane >> 4) & 1) * 4;
    const int b_off = (wn * 32 + ((lane >> 4) & 1) * 8 + (lane & 7)) * XPAD
                    + ((lane >> 3) & 1) * 4;
    const unsigned aAddr0 = smem_b + (unsigned)(a_off * 4);
    const unsigned bAddr0 = smem_b + (unsigned)((SX_U32 + b_off) * 4);

    auto load_stage = [&](int stage, int kt) {
        unsigned* sX = smem + stage * STAGE_U32;
        unsigned* sW = sX + SX_U32;
        int kc = kt * BK;
        for (int idx = tid; idx < 516; idx += 256) {          // X: 129 rows x 32 halves
            int r = idx >> 2, c4 = idx & 3;
            int t = t0 - 1 + r;
            const __half* src = Xb + (size_t)(t < 0 ? 0 : t) * CC + kc + c4 * 8;
            cpa16(&sX[r * XPAD + c4 * 4], src, t >= 0);
        }
        for (int idx = tid; idx < 1024; idx += 256) {         // W: 2 taps x 128 n x 32 halves
            int tap = idx >> 9, rem = idx & 511, n = rem >> 2, c4 = rem & 3;
            const __half* src = Wl + ((size_t)tap * NOUT + nt * BN + n) * CC + kc + c4 * 8;
            cpa16(&sW[(tap * BN + n) * XPAD + c4 * 4], src, true);
        }
        asm volatile("cp.async.commit_group;" ::: "memory");
    };

    load_stage(0, 0);
    load_stage(1, 1);

    for (int kt = 0; kt < NKT; kt++) {
        if (kt == NKT - 1) asm volatile("cp.async.wait_group 0;" ::: "memory");
        else               asm volatile("cp.async.wait_group 1;" ::: "memory");
        __syncthreads();

        if (kt + 2 < NKT) load_stage((kt + 2) % STG, kt + 2);

        const unsigned stageB = (unsigned)((kt % STG) * (STAGE_U32 * 4));
        const unsigned aS = aAddr0 + stageB;
        const unsigned bS = bAddr0 + stageB;

#pragma unroll
        for (int k16 = 0; k16 < 2; ++k16) {
#pragma unroll
            for (int tap = 0; tap < 2; ++tap) {
                unsigned afr[4][4], bfr[2][4];
#pragma unroll
                for (int i = 0; i < 4; i++)
                    ldsm4(afr[i], aS + (unsigned)((i * 16 * XPAD + tap * XPAD + k16 * 8) * 4));
#pragma unroll
                for (int jp = 0; jp < 2; jp++)
                    ldsm4(bfr[jp], bS + (unsigned)((jp * 16 * XPAD + tap * BN * XPAD + k16 * 8) * 4));
#pragma unroll
                for (int j = 0; j < 4; j++) {
                    unsigned b0 = bfr[j >> 1][(j & 1) * 2];
                    unsigned b1 = bfr[j >> 1][(j & 1) * 2 + 1];
#pragma unroll
                    for (int i = 0; i < 4; i++) mma16(acc[i][j], afr[i], b0, b1);
                }
            }
        }
    }

    // ---- epilogue: bias + activation -> split fp16 gate arrays ----
    const int gate = nt >> 2;                 // 0=z, 1=f, 2=o
#pragma unroll
    for (int j = 0; j < 4; j++) {
        int ngl = nt * BN + wn * 32 + j * 8 + tg * 2;       // global 0..1535
        int hh  = ngl - gate * HH;                          // 0..511
        float2 bb = *(const float2*)&bias[ngl];
#pragma unroll
        for (int i = 0; i < 4; i++) {
            int tA = t0 + wm * 64 + i * 16 + gr;
            size_t rowA = (size_t)(b * TT + tA) * HH + hh;
            size_t rowB = rowA + (size_t)8 * HH;
            float a0 = acc[i][j][0] + bb.x, a1 = acc[i][j][1] + bb.y;
            float a2 = acc[i][j][2] + bb.x, a3 = acc[i][j][3] + bb.y;
            if (gate == 0) {
                *(__half2*)&g_z[rowA] = __floats2half2_rn(ftanh(a0), ftanh(a1));
                *(__half2*)&g_z[rowB] = __floats2half2_rn(ftanh(a2), ftanh(a3));
            } else if (gate == 1) {
                *(__half2*)&g_fh[rowA] = __floats2half2_rn(fsigmoid(a0), fsigmoid(a1));
                *(__half2*)&g_fh[rowB] = __floats2half2_rn(fsigmoid(a2), fsigmoid(a3));
            } else {
                *(__half2*)&g_o[rowA] = __floats2half2_rn(fsigmoid(a0), fsigmoid(a1));
                *(__half2*)&g_o[rowB] = __floats2half2_rn(fsigmoid(a2), fsigmoid(a3));
            }
        }
    }
}

// ---------------- fused scan pass1 + pass2 ----------------
// grid BB*NC = 1024, block 128. Each block: chunk aggregates (A = prod f,
// B = local scan end). Last-finishing block of each batch b performs the
// 128-chunk sequential combine for all 512 h-channels of that batch.
__global__ void __launch_bounds__(128) scan_p12(float* __restrict__ hT)
{
    int b  = blockIdx.x / NC;
    int ch = blockIdx.x % NC;
    int h4 = threadIdx.x * 4;
    size_t base = ((size_t)(b * TT + ch * LCH)) * HH + h4;
    const __half2* pf = (const __half2*)(g_fh + base);
    const __half2* pz = (const __half2*)(g_z + base);
    float4 A  = make_float4(1.f, 1.f, 1.f, 1.f);
    float4 hv = make_float4(0.f, 0.f, 0.f, 0.f);
#pragma unroll 8
    for (int i = 0; i < LCH; i++) {
        float2 fa = __half22float2(pf[0]);
        float2 fb = __half22float2(pf[1]);
        float2 za = __half22float2(pz[0]);
        float2 zb = __half22float2(pz[1]);
        hv.x = fa.x * hv.x + (1.0f - fa.x) * za.x;  A.x *= fa.x;
        hv.y = fa.y * hv.y + (1.0f - fa.y) * za.y;  A.y *= fa.y;
        hv.z = fb.x * hv.z + (1.0f - fb.x) * zb.x;  A.z *= fb.x;
        hv.w = fb.y * hv.w + (1.0f - fb.y) * zb.y;  A.w *= fb.y;
        pf += HH / 2; pz += HH / 2;
    }
    int o = (b * NC + ch) * HH + h4;
    *(float4*)&g_cA[o] = A;
    *(float4*)&g_cB[o] = hv;

    // ---- last-block-per-batch combine ----
    __shared__ int amLast;
    __threadfence();                 // each thread publishes its aggregate stores
    __syncthreads();
    if (threadIdx.x == 0) {
        unsigned prev = atomicAdd(&g_cnt[b], 1u);
        amLast = (prev == NC - 1);
    }
    __syncthreads();
    if (amLast) {
        __threadfence();             // acquire side
        const size_t cb = (size_t)b * NC * HH + h4;
        float4 hr = make_float4(0.f, 0.f, 0.f, 0.f);
#pragma unroll
        for (int jb = 0; jb < NC; jb += 8) {
            float4 a[8], v[8];
#pragma unroll
            for (int k = 0; k < 8; k++) {
                a[k] = *(const float4*)&g_cA[cb + (size_t)(jb + k) * HH];
                v[k] = *(const float4*)&g_cB[cb + (size_t)(jb + k) * HH];
            }
#pragma unroll
            for (int k = 0; k < 8; k++) {
                *(float4*)&g_hs[cb + (size_t)(jb + k) * HH] = hr;
                hr.x = a[k].x * hr.x + v[k].x;
                hr.y = a[k].y * hr.y + v[k].y;
                hr.z = a[k].z * hr.z + v[k].z;
                hr.w = a[k].w * hr.w + v[k].w;
            }
        }
        *(float4*)&hT[b * HH + h4] = hr;
        if (threadIdx.x == 0) g_cnt[b] = 0;   // reset for next launch (replay-safe)
    }
}

// layer 0: writes fp16 g_xh2.  layer 1: writes fp32 d_out.
__global__ void __launch_bounds__(128) scan_pass3(int layer, float* __restrict__ dout)
{
    int b  = blockIdx.x / NC;
    int ch = blockIdx.x % NC;
    int h4 = threadIdx.x * 4;
    size_t base = ((size_t)(b * TT + ch * LCH)) * HH + h4;
    const __half2* pf = (const __half2*)(g_fh + base);
    const __half2* pz = (const __half2*)(g_z + base);
    const __half2* po = (const __half2*)(g_o + base);
    float4 hv = *(const float4*)&g_hs[(b * NC + ch) * HH + h4];
#pragma unroll 4
    for (int i = 0; i < LCH; i++) {
        int t = ch * LCH + i;
        float2 fa = __half22float2(pf[0]);
        float2 fb = __half22float2(pf[1]);
        float2 za = __half22float2(pz[0]);
        float2 zb = __half22float2(pz[1]);
        float2 oa = __half22float2(po[0]);
        float2 ob = __half22float2(po[1]);
        hv.x = fa.x * hv.x + (1.0f - fa.x) * za.x;
        hv.y = fa.y * hv.y + (1.0f - fa.y) * za.y;
        hv.z = fb.x * hv.z + (1.0f - fb.x) * zb.x;
        hv.w = fb.y * hv.w + (1.0f - fb.y) * zb.y;
        float4 r = make_float4(oa.x * hv.x, oa.y * hv.y, ob.x * hv.z, ob.y * hv.w);
        if (!layer) {
            __half2 p0 = __floats2half2_rn(r.x, r.y);
            __half2 p1 = __floats2half2_rn(r.z, r.w);
            uint2 st;
            st.x = *(unsigned*)&p0;
            st.y = *(unsigned*)&p1;
            *(uint2*)&g_xh2[((size_t)b * TT + t) * CC + h4] = st;
        } else {
            *(float4*)&dout[((size_t)b * TT + t) * HH + h4] = r;
        }
        pf += HH / 2; pz += HH / 2; po += HH / 2;
    }
}

extern "C" void kernel_launch(void* const* d_in, const int* in_sizes, int n_in,
                              void* d_out, int out_size)
{
    const float* x  = (const float*)d_in[0];
    const float* w0 = (const float*)d_in[1];
    const float* b0 = (const float*)d_in[2];
    const float* w1 = (const float*)d_in[3];
    const float* b1 = (const float*)d_in[4];

    float* out2 = (float*)d_out;
    float* h0   = out2 + (size_t)BB * TT * HH;
    float* h1   = h0 + BB * HH;

    cudaFuncSetAttribute(qrnn_gemm, cudaFuncAttributeMaxDynamicSharedMemorySize, SMEM_BYTES);

    cvt_in<<<XBLKS + WBLKS, 256>>>(x, w0, w1);

    dim3 gg(NOUT / BN, BB * TT / BM);   // (12, 256)

    qrnn_gemm<<<gg, 256, SMEM_BYTES>>>(0, b0);
    scan_p12<<<BB * NC, 128>>>(h0);
    scan_pass3<<<BB * NC, 128>>>(0, nullptr);

    qrnn_gemm<<<gg, 256, SMEM_BYTES>>>(1, b1);
    scan_p12<<<BB * NC, 128>>>(h1);
    scan_pass3<<<BB * NC, 128>>>(1, out2);
}

// round 17
// speedup vs baseline: 1.5378x; 1.5378x over previous
#include <cuda_runtime.h>
#include <cuda_fp16.h>
#include <math.h>

#define BB 8
#define TT 4096
#define CC 512
#define HH 512
#define NOUT 1536
#define NC 256
#define LCH 16

#define BM 128
#define BN 128
#define BK 32                 // halves per k-tile
#define NKT 16                // 512 / 32
#define STG 3
#define XPAD 20               // row stride in b32 units (conflict-free, 16B-aligned)
#define SX_U32 (129 * XPAD)   // 2580
#define SW_U32 (256 * XPAD)   // 5120
#define STAGE_U32 (SX_U32 + SW_U32)
#define SMEM_BYTES (STG * STAGE_U32 * 4)

#define XBLKS (BB * TT * CC / 8 / 256)     // 8192
#define WBLKS (2 * NOUT * CC / 256)        // 6144

// -------- scratch --------
__device__ __align__(16) __half g_xh [(size_t)BB * TT * CC];      // fp16 input x
__device__ __align__(16) __half g_xh2[(size_t)BB * TT * CC];      // fp16 layer-1 output
__device__ __align__(16) __half g_wh [(size_t)2 * 2 * NOUT * CC]; // [layer][tap][n][c]
__device__ __align__(16) __half g_z  [(size_t)BB * TT * HH];      // tanh(z)   fp16
__device__ __align__(16) __half g_fh [(size_t)BB * TT * HH];      // sig(f)    fp16
__device__ __align__(16) __half g_o  [(size_t)BB * TT * HH];      // sig(o)    fp16
__device__ __align__(16) float  g_cA [BB * NC * HH];
__device__ __align__(16) float  g_cB [BB * NC * HH];
__device__ __align__(16) float  g_hs [BB * NC * HH];

__device__ __forceinline__ void cpa16(unsigned* dst_smem_word, const void* src, bool pred) {
    unsigned d = (unsigned)__cvta_generic_to_shared(dst_smem_word);
    int sz = pred ? 16 : 0;
    asm volatile("cp.async.cg.shared.global [%0], [%1], 16, %2;\n"
                 :: "r"(d), "l"(src), "r"(sz) : "memory");
}

__device__ __forceinline__ void mma16(float* c, const unsigned* a, unsigned b0, unsigned b1) {
    asm volatile(
        "mma.sync.aligned.m16n8k16.row.col.f32.f16.f16.f32 "
        "{%0,%1,%2,%3}, {%4,%5,%6,%7}, {%8,%9}, {%0,%1,%2,%3};\n"
        : "+f"(c[0]), "+f"(c[1]), "+f"(c[2]), "+f"(c[3])
        : "r"(a[0]), "r"(a[1]), "r"(a[2]), "r"(a[3]), "r"(b0), "r"(b1));
}

__device__ __forceinline__ void ldsm4(unsigned* r, unsigned addr) {
    asm volatile("ldmatrix.sync.aligned.m8n8.x4.shared.b16 {%0,%1,%2,%3}, [%4];"
                 : "=r"(r[0]), "=r"(r[1]), "=r"(r[2]), "=r"(r[3]) : "r"(addr));
}

// fast activations: EX2-based exp + MUFU.RCP division
__device__ __forceinline__ float fsigmoid(float x) {
    return __fdividef(1.0f, 1.0f + __expf(-x));
}
__device__ __forceinline__ float ftanh(float x) {
    return 2.0f * __fdividef(1.0f, 1.0f + __expf(-2.0f * x)) - 1.0f;
}

// ---------------- prep: fp16 conversion (x and w fused) ----------------
__global__ void cvt_in(const float* __restrict__ x,
                       const float* __restrict__ w0, const float* __restrict__ w1) {
    int bid = blockIdx.x;
    if (bid < XBLKS) {
        int gid = bid * blockDim.x + threadIdx.x;
        float4 v0 = ((const float4*)x)[gid * 2];
        float4 v1 = ((const float4*)x)[gid * 2 + 1];
        __half2 h0 = __floats2half2_rn(v0.x, v0.y);
        __half2 h1 = __floats2half2_rn(v0.z, v0.w);
        __half2 h2 = __floats2half2_rn(v1.x, v1.y);
        __half2 h3 = __floats2half2_rn(v1.z, v1.w);
        uint4 o;
        o.x = *(unsigned*)&h0; o.y = *(unsigned*)&h1;
        o.z = *(unsigned*)&h2; o.w = *(unsigned*)&h3;
        ((uint4*)g_xh)[gid] = o;
    } else {
        int gid = (bid - XBLKS) * blockDim.x + threadIdx.x;   // 0 .. 2*NOUT*CC-1
        int layer = gid >= NOUT * CC;
        int r = gid - layer * NOUT * CC;
        int n = r / CC, c = r % CC;
        const float* w = layer ? w1 : w0;
        float2 v = *(const float2*)(w + ((size_t)n * CC + c) * 2);
        g_wh[(((size_t)layer * 2 + 0) * NOUT + n) * CC + c] = __float2half_rn(v.x); // tap0
        g_wh[(((size_t)layer * 2 + 1) * NOUT + n) * CC + c] = __float2half_rn(v.y); // tap1
    }
}

// ---------------- fp16 HMMA GEMM + activation ----------------
// grid (12, 256): x = N-tile (fast: shares A stripe via L2), y = M-tile. block 256.
// 8 warps in 2(M) x 4(N), warp tile 64x32, acc 64 regs -> 2 CTAs/SM.
__global__ void __launch_bounds__(256, 2) qrnn_gemm(int layer, const float* __restrict__ bias)
{
    extern __shared__ unsigned smem[];

    const __half* X  = layer ? g_xh2 : g_xh;
    const __half* Wl = g_wh + (size_t)layer * 2 * NOUT * CC;

    const int tid  = threadIdx.x;
    const int nt   = blockIdx.x;
    const int mt   = blockIdx.y;
    const int b    = mt >> 5;
    const int t0   = (mt & 31) * BM;
    const int warp = tid >> 5, lane = tid & 31;
    const int wm   = warp >> 2, wn = warp & 3;
    const int gr   = lane >> 2, tg = lane & 3;

    const __half* Xb = X + (size_t)b * TT * CC;

    float acc[4][4][4];
#pragma unroll
    for (int i = 0; i < 4; i++)
#pragma unroll
        for (int j = 0; j < 4; j++)
#pragma unroll
            for (int q = 0; q < 4; q++) acc[i][j][q] = 0.0f;

    // ---- per-lane ldmatrix base addresses (bytes into stage 0) ----
    const unsigned smem_b = (unsigned)__cvta_generic_to_shared(smem);
    const int a_off = (wm * 64 + (lane & 7) + ((lane >> 3) & 1) * 8) * XPAD
                    + ((lane >> 4) & 1) * 4;
    const int b_off = (wn * 32 + ((lane >> 4) & 1) * 8 + (lane & 7)) * XPAD
                    + ((lane >> 3) & 1) * 4;
    const unsigned aAddr0 = smem_b + (unsigned)(a_off * 4);
    const unsigned bAddr0 = smem_b + (unsigned)((SX_U32 + b_off) * 4);

    auto load_stage = [&](int stage, int kt) {
        unsigned* sX = smem + stage * STAGE_U32;
        unsigned* sW = sX + SX_U32;
        int kc = kt * BK;
        for (int idx = tid; idx < 516; idx += 256) {          // X: 129 rows x 32 halves
            int r = idx >> 2, c4 = idx & 3;
            int t = t0 - 1 + r;
            const __half* src = Xb + (size_t)(t < 0 ? 0 : t) * CC + kc + c4 * 8;
            cpa16(&sX[r * XPAD + c4 * 4], src, t >= 0);
        }
        for (int idx = tid; idx < 1024; idx += 256) {         // W: 2 taps x 128 n x 32 halves
            int tap = idx >> 9, rem = idx & 511, n = rem >> 2, c4 = rem & 3;
            const __half* src = Wl + ((size_t)tap * NOUT + nt * BN + n) * CC + kc + c4 * 8;
            cpa16(&sW[(tap * BN + n) * XPAD + c4 * 4], src, true);
        }
        asm volatile("cp.async.commit_group;" ::: "memory");
    };

    load_stage(0, 0);
    load_stage(1, 1);

    for (int kt = 0; kt < NKT; kt++) {
        if (kt == NKT - 1) asm volatile("cp.async.wait_group 0;" ::: "memory");
        else               asm volatile("cp.async.wait_group 1;" ::: "memory");
        __syncthreads();

        if (kt + 2 < NKT) load_stage((kt + 2) % STG, kt + 2);

        const unsigned stageB = (unsigned)((kt % STG) * (STAGE_U32 * 4));
        const unsigned aS = aAddr0 + stageB;
        const unsigned bS = bAddr0 + stageB;

#pragma unroll
        for (int k16 = 0; k16 < 2; ++k16) {
#pragma unroll
            for (int tap = 0; tap < 2; ++tap) {
                unsigned afr[4][4], bfr[2][4];
#pragma unroll
                for (int i = 0; i < 4; i++)
                    ldsm4(afr[i], aS + (unsigned)((i * 16 * XPAD + tap * XPAD + k16 * 8) * 4));
#pragma unroll
                for (int jp = 0; jp < 2; jp++)
                    ldsm4(bfr[jp], bS + (unsigned)((jp * 16 * XPAD + tap * BN * XPAD + k16 * 8) * 4));
#pragma unroll
                for (int j = 0; j < 4; j++) {
                    unsigned b0 = bfr[j >> 1][(j & 1) * 2];
                    unsigned b1 = bfr[j >> 1][(j & 1) * 2 + 1];
#pragma unroll
                    for (int i = 0; i < 4; i++) mma16(acc[i][j], afr[i], b0, b1);
                }
            }
        }
    }

    // ---- epilogue: bias + activation -> split fp16 gate arrays ----
    const int gate = nt >> 2;                 // 0=z, 1=f, 2=o
#pragma unroll
    for (int j = 0; j < 4; j++) {
        int ngl = nt * BN + wn * 32 + j * 8 + tg * 2;       // global 0..1535
        int hh  = ngl - gate * HH;                          // 0..511
        float2 bb = *(const float2*)&bias[ngl];
#pragma unroll
        for (int i = 0; i < 4; i++) {
            int tA = t0 + wm * 64 + i * 16 + gr;
            size_t rowA = (size_t)(b * TT + tA) * HH + hh;
            size_t rowB = rowA + (size_t)8 * HH;
            float a0 = acc[i][j][0] + bb.x, a1 = acc[i][j][1] + bb.y;
            float a2 = acc[i][j][2] + bb.x, a3 = acc[i][j][3] + bb.y;
            if (gate == 0) {
                *(__half2*)&g_z[rowA] = __floats2half2_rn(ftanh(a0), ftanh(a1));
                *(__half2*)&g_z[rowB] = __floats2half2_rn(ftanh(a2), ftanh(a3));
            } else if (gate == 1) {
                *(__half2*)&g_fh[rowA] = __floats2half2_rn(fsigmoid(a0), fsigmoid(a1));
                *(__half2*)&g_fh[rowB] = __floats2half2_rn(fsigmoid(a2), fsigmoid(a3));
            } else {
                *(__half2*)&g_o[rowA] = __floats2half2_rn(fsigmoid(a0), fsigmoid(a1));
                *(__half2*)&g_o[rowB] = __floats2half2_rn(fsigmoid(a2), fsigmoid(a3));
            }
        }
    }
}

// ---------------- scans ----------------
__global__ void __launch_bounds__(128) scan_pass1()
{
    int b  = blockIdx.x / NC;
    int ch = blockIdx.x % NC;
    int h4 = threadIdx.x * 4;
    size_t base = ((size_t)(b * TT + ch * LCH)) * HH + h4;
    const __half2* pf = (const __half2*)(g_fh + base);
    const __half2* pz = (const __half2*)(g_z + base);
    float4 A  = make_float4(1.f, 1.f, 1.f, 1.f);
    float4 hv = make_float4(0.f, 0.f, 0.f, 0.f);
#pragma unroll 8
    for (int i = 0; i < LCH; i++) {
        float2 fa = __half22float2(pf[0]);
        float2 fb = __half22float2(pf[1]);
        float2 za = __half22float2(pz[0]);
        float2 zb = __half22float2(pz[1]);
        hv.x = fa.x * hv.x + (1.0f - fa.x) * za.x;  A.x *= fa.x;
        hv.y = fa.y * hv.y + (1.0f - fa.y) * za.y;  A.y *= fa.y;
        hv.z = fb.x * hv.z + (1.0f - fb.x) * zb.x;  A.z *= fb.x;
        hv.w = fb.y * hv.w + (1.0f - fb.y) * zb.y;  A.w *= fb.y;
        pf += HH / 2; pz += HH / 2;
    }
    int o = (b * NC + ch) * HH + h4;
    *(float4*)&g_cA[o] = A;
    *(float4*)&g_cB[o] = hv;
}

// sequential combine with batched loads (MLP=16). grid 32, block 128.
__global__ void __launch_bounds__(128) scan_pass2(float* __restrict__ hT)
{
    int gid = blockIdx.x * blockDim.x + threadIdx.x;   // 0..4095
    int b = gid >> 9, h = gid & 511;
    const float* pa = g_cA + (size_t)b * NC * HH + h;
    const float* pb = g_cB + (size_t)b * NC * HH + h;
    float*       ps = g_hs + (size_t)b * NC * HH + h;
    float hr = 0.0f;
#pragma unroll
    for (int jb = 0; jb < NC; jb += 8) {
        float a[8], v[8];
#pragma unroll
        for (int k = 0; k < 8; k++) {
            a[k] = pa[(size_t)(jb + k) * HH];
            v[k] = pb[(size_t)(jb + k) * HH];
        }
#pragma unroll
        for (int k = 0; k < 8; k++) {
            ps[(size_t)(jb + k) * HH] = hr;
            hr = a[k] * hr + v[k];
        }
    }
    hT[b * HH + h] = hr;
}

// layer 0: writes fp16 g_xh2.  layer 1: writes fp32 d_out.
__global__ void __launch_bounds__(128) scan_pass3(int layer, float* __restrict__ dout)
{
    int b  = blockIdx.x / NC;
    int ch = blockIdx.x % NC;
    int h4 = threadIdx.x * 4;
    size_t base = ((size_t)(b * TT + ch * LCH)) * HH + h4;
    const __half2* pf = (const __half2*)(g_fh + base);
    const __half2* pz = (const __half2*)(g_z + base);
    const __half2* po = (const __half2*)(g_o + base);
    float4 hv = *(const float4*)&g_hs[(b * NC + ch) * HH + h4];
#pragma unroll 4
    for (int i = 0; i < LCH; i++) {
        int t = ch * LCH + i;
        float2 fa = __half22float2(pf[0]);
        float2 fb = __half22float2(pf[1]);
        float2 za = __half22float2(pz[0]);
        float2 zb = __half22float2(pz[1]);
        float2 oa = __half22float2(po[0]);
        float2 ob = __half22float2(po[1]);
        hv.x = fa.x * hv.x + (1.0f - fa.x) * za.x;
        hv.y = fa.y * hv.y + (1.0f - fa.y) * za.y;
        hv.z = fb.x * hv.z + (1.0f - fb.x) * zb.x;
        hv.w = fb.y * hv.w + (1.0f - fb.y) * zb.y;
        float4 r = make_float4(oa.x * hv.x, oa.y * hv.y, ob.x * hv.z, ob.y * hv.w);
        if (!layer) {
            __half2 p0 = __floats2half2_rn(r.x, r.y);
            __half2 p1 = __floats2half2_rn(r.z, r.w);
            uint2 st;
            st.x = *(unsigned*)&p0;
            st.y = *(unsigned*)&p1;
            *(uint2*)&g_xh2[((size_t)b * TT + t) * CC + h4] = st;
        } else {
            *(float4*)&dout[((size_t)b * TT + t) * HH + h4] = r;
        }
        pf += HH / 2; pz += HH / 2; po += HH / 2;
    }
}

extern "C" void kernel_launch(void* const* d_in, const int* in_sizes, int n_in,
                              void* d_out, int out_size)
{
    const float* x  = (const float*)d_in[0];
    const float* w0 = (const float*)d_in[1];
    const float* b0 = (const float*)d_in[2];
    const float* w1 = (const float*)d_in[3];
    const float* b1 = (const float*)d_in[4];

    float* out2 = (float*)d_out;
    float* h0   = out2 + (size_t)BB * TT * HH;
    float* h1   = h0 + BB * HH;

    cudaFuncSetAttribute(qrnn_gemm, cudaFuncAttributeMaxDynamicSharedMemorySize, SMEM_BYTES);

    cvt_in<<<XBLKS + WBLKS, 256>>>(x, w0, w1);

    dim3 gg(NOUT / BN, BB * TT / BM);   // (12, 256)

    qrnn_gemm<<<gg, 256, SMEM_BYTES>>>(0, b0);
    scan_pass1<<<BB * NC, 128>>>();
    scan_pass2<<<32, 128>>>(h0);
    scan_pass3<<<BB * NC, 128>>>(0, nullptr);

    qrnn_gemm<<<gg, 256, SMEM_BYTES>>>(1, b1);
    scan_pass1<<<BB * NC, 128>>>();
    scan_pass2<<<32, 128>>>(h1);
    scan_pass3<<<BB * NC, 128>>>(1, out2);
}